// round 3
// baseline (speedup 1.0000x reference)
#include <cuda_runtime.h>
#include <cstdint>

#define BT    32
#define P     34
#define NTHR  256
typedef unsigned long long ull;

// ---------------- persistent device scratch (static, no allocations) ----------------
__device__ __align__(16) float g_W1T[784*128];   // [k][j]
__device__ __align__(16) float g_M1T[128*128];   // -(W1@fb1)^T, k-major
__device__ __align__(16) float g_U1T[128*128];
__device__ __align__(16) float g_W2T[128*64];
__device__ __align__(16) float g_M2T[64*64];     // negated
__device__ __align__(16) float g_U2T[64*64];
__device__ __align__(16) float g_W3T[64*32];
__device__ __align__(16) float g_M3T[32*32];     // negated
__device__ __align__(16) float g_U3T[32*32];
__device__ __align__(16) float g_c1[128];
__device__ __align__(16) float g_c2[64];
__device__ __align__(16) float g_c3[32];

// ---------------- helpers ----------------
__device__ __forceinline__ ull dup2(float x) {
    ull r;
    asm("mov.b64 %0, {%1, %1};" : "=l"(r) : "f"(x));
    return r;
}
__device__ __forceinline__ void up2(ull v, float &lo, float &hi) {
    asm("mov.b64 {%0, %1}, %2;" : "=f"(lo), "=f"(hi) : "l"(v));
}
__device__ __forceinline__ void fma2(ull &d, ull a, ull b) {
    asm("fma.rn.f32x2 %0, %1, %2, %0;" : "+l"(d) : "l"(a), "l"(b));
}
// tanh(x) = 1 - 2/(1 + e^{2x}) via MUFU.EX2 + MUFU.RCP  (~1e-6 abs err)
__device__ __forceinline__ float ftanh(float x) {
    float e, r;
    asm("ex2.approx.ftz.f32 %0, %1;" : "=f"(e) : "f"(x * 2.8853900817779268f));
    asm("rcp.approx.ftz.f32 %0, %1;" : "=f"(r) : "f"(e + 1.0f));
    return fmaf(-2.0f, r, 1.0f);
}

// single-matrix GEMM: A feature-major [K][P] smem, B k-major [K][LDB]
// thread computes rows (i0,i0+1) x cols (j0..j0+2*NP-1)
template<int K, int NP, int LDB, int UNR>
__device__ __forceinline__ void gemm1(const float* __restrict__ A,
                                      const float* __restrict__ B,
                                      int i0, int j0, ull (&acc)[2][NP]) {
#pragma unroll UNR
    for (int k = 0; k < K; k++) {
        float2 a2 = *reinterpret_cast<const float2*>(A + k * P + i0);
        const float* br = B + k * LDB + j0;
        ull b[NP];
#pragma unroll
        for (int p = 0; p < NP; p++)
            b[p] = *reinterpret_cast<const ull*>(br + 2 * p);
        ull A0 = dup2(a2.x), A1 = dup2(a2.y);
#pragma unroll
        for (int p = 0; p < NP; p++) {
            fma2(acc[0][p], A0, b[p]);
            fma2(acc[1][p], A1, b[p]);
        }
    }
}

// fused two-matrix GEMM (shared A): B1 -> acc1, B2 -> acc2
template<int K, int NP, int LDB, int UNR>
__device__ __forceinline__ void gemm2(const float* __restrict__ A,
                                      const float* __restrict__ B1,
                                      const float* __restrict__ B2,
                                      int i0, int j0,
                                      ull (&acc1)[2][NP], ull (&acc2)[2][NP]) {
#pragma unroll UNR
    for (int k = 0; k < K; k++) {
        float2 a2 = *reinterpret_cast<const float2*>(A + k * P + i0);
        const float* b1r = B1 + k * LDB + j0;
        const float* b2r = B2 + k * LDB + j0;
        ull b1[NP], b2[NP];
#pragma unroll
        for (int p = 0; p < NP; p++) {
            b1[p] = *reinterpret_cast<const ull*>(b1r + 2 * p);
            b2[p] = *reinterpret_cast<const ull*>(b2r + 2 * p);
        }
        ull A0 = dup2(a2.x), A1 = dup2(a2.y);
#pragma unroll
        for (int p = 0; p < NP; p++) {
            fma2(acc1[0][p], A0, b1[p]);
            fma2(acc1[1][p], A1, b1[p]);
            fma2(acc2[0][p], A0, b2[p]);
            fma2(acc2[1][p], A1, b2[p]);
        }
    }
}

// ---------------- merged prep kernel ----------------
// blocks 0..127  : M1 row j (K=784) + c1[j]
// blocks 128..191: M2 row j (K=128) + c2[j]
// blocks 192..223: M3 row j (K=64)  + c3[j]
// blocks 224..255: all transposes, grid-strided
__global__ void prep_all(const float* __restrict__ W1w, const float* __restrict__ W1b,
                         const float* __restrict__ U1w,
                         const float* __restrict__ W2w, const float* __restrict__ W2b,
                         const float* __restrict__ U2w,
                         const float* __restrict__ W3w, const float* __restrict__ W3b,
                         const float* __restrict__ U3w,
                         const float* __restrict__ fb3w, const float* __restrict__ fb3b,
                         const float* __restrict__ fb2w, const float* __restrict__ fb2b,
                         const float* __restrict__ fb1w, const float* __restrict__ fb1b) {
    __shared__ float row_s[784];
    __shared__ float red_s[128];
    const int bid = blockIdx.x;
    const int tid = threadIdx.x;   // 128 threads

    if (bid < 128) {
        const int j = bid;
        for (int d = tid; d < 784; d += 128) row_s[d] = W1w[j * 784 + d];
        __syncthreads();
        // M1T column j
        {
            const int k = tid;
            float s = 0.f;
#pragma unroll 4
            for (int d = 0; d < 784; d++) s += row_s[d] * fb1w[d * 128 + k];
            g_M1T[k * 128 + j] = -s;
        }
        // c1[j] = W1b[j] - dot(row, fb1b)
        float ps = 0.f;
        for (int d = tid; d < 784; d += 128) ps += row_s[d] * fb1b[d];
        red_s[tid] = ps;
        __syncthreads();
        for (int off = 64; off > 0; off >>= 1) {
            if (tid < off) red_s[tid] += red_s[tid + off];
            __syncthreads();
        }
        if (tid == 0) g_c1[j] = W1b[j] - red_s[0];
    } else if (bid < 192) {
        const int j = bid - 128;
        for (int d = tid; d < 128; d += 128) row_s[d] = W2w[j * 128 + d];
        __syncthreads();
        if (tid < 64) {
            const int k = tid;
            float s = 0.f;
#pragma unroll 4
            for (int d = 0; d < 128; d++) s += row_s[d] * fb2w[d * 64 + k];
            g_M2T[k * 64 + j] = -s;
        }
        float ps = 0.f;
        if (tid < 128) for (int d = tid; d < 128; d += 128) ps += row_s[d] * fb2b[d];
        red_s[tid] = ps;
        __syncthreads();
        for (int off = 64; off > 0; off >>= 1) {
            if (tid < off) red_s[tid] += red_s[tid + off];
            __syncthreads();
        }
        if (tid == 0) g_c2[j] = W2b[j] - red_s[0];
    } else if (bid < 224) {
        const int j = bid - 192;
        for (int d = tid; d < 64; d += 128) row_s[d] = W3w[j * 64 + d];
        __syncthreads();
        if (tid < 32) {
            const int k = tid;
            float s = 0.f;
#pragma unroll 4
            for (int d = 0; d < 64; d++) s += row_s[d] * fb3w[d * 32 + k];
            g_M3T[k * 32 + j] = -s;
        }
        float ps = 0.f;
        for (int d = tid; d < 64; d += 128) ps += row_s[d] * fb3b[d];
        red_s[tid] = ps;
        __syncthreads();
        for (int off = 64; off > 0; off >>= 1) {
            if (tid < off) red_s[tid] += red_s[tid + off];
            __syncthreads();
        }
        if (tid == 0) g_c3[j] = W3b[j] - red_s[0];
    } else {
        const int idx0 = (bid - 224) * 128 + tid;
        const int stride = 32 * 128;
        for (int t = idx0; t < 784 * 128; t += stride) {
            int k = t >> 7, j = t & 127;
            g_W1T[t] = W1w[j * 784 + k];
        }
        for (int t = idx0; t < 128 * 128; t += stride) {
            int k = t >> 7, j = t & 127;
            g_U1T[t] = U1w[j * 128 + k];
        }
        for (int t = idx0; t < 128 * 64; t += stride) {
            int k = t >> 6, j = t & 63;
            g_W2T[t] = W2w[j * 128 + k];
        }
        for (int t = idx0; t < 64 * 64; t += stride) {
            int k = t >> 6, j = t & 63;
            g_U2T[t] = U2w[j * 64 + k];
        }
        for (int t = idx0; t < 64 * 32; t += stride) {
            int k = t >> 5, j = t & 31;
            g_W3T[t] = W3w[j * 64 + k];
        }
        for (int t = idx0; t < 32 * 32; t += stride) {
            int k = t >> 5, j = t & 31;
            g_U3T[t] = U3w[j * 32 + k];
        }
    }
}

// ---------------- main kernel ----------------
// smem (floats):
//   h1s [128][34] @ 0      (4352)
//   h2s [ 64][34] @ 4352   (2176)
//   h3s [ 32][34] @ 6528   (1088)
//   weights @ 7616 (49152):
//     sM1 @ 7616  (16384)   sU1 @ 24000 (16384)
//     sW2 @ 40384 (8192)    sM2 @ 48576 (4096)   sU2 @ 52672 (4096)
//   phase-1 overlay in weight region:
//     xst  @ 7616  [32][784] (25088)
//     wchk @ 32704 [112][128] (14336)
// total 56768 floats = 227072 B
__global__ void __launch_bounds__(NTHR, 1)
pcnet_main(const float* __restrict__ x,
           const float* __restrict__ U1b, const float* __restrict__ U2b,
           const float* __restrict__ U3b,
           const float* __restrict__ clfw, const float* __restrict__ clfb,
           const int* __restrict__ steps_p,
           float* __restrict__ out) {
    extern __shared__ float sm[];
    float* h1s = sm;
    float* h2s = sm + 4352;
    float* h3s = sm + 6528;
    float* sM1 = sm + 7616;
    float* sU1 = sm + 24000;
    float* sW2 = sm + 40384;
    float* sM2 = sm + 48576;
    float* sU2 = sm + 52672;
    float* xst = sm + 7616;    // overlay
    float* wch = sm + 32704;   // overlay

    const int tid  = threadIdx.x;
    const int row0 = blockIdx.x * BT;
    const int iIdx = tid >> 4;        // 0..15
    const int jIdx = tid & 15;        // 0..15
    const int i0   = iIdx * 2;        // rows i0, i0+1

    // zero states
    for (int i = tid; i < 224 * P; i += NTHR) sm[i] = 0.f;

    int steps = *steps_p;
    if (steps < 0 || steps > 64) steps = 5;

    // ---- phase 1: xw = x @ W1^T + c1, kept in registers ----
    float xwv[2][8];
    {
        // stage x tile [32][784]
        for (int idx = tid; idx < 32 * 196; idx += NTHR) {
            int r = idx / 196, c4 = idx - r * 196;
            *reinterpret_cast<float4*>(xst + r * 784 + c4 * 4) =
                *reinterpret_cast<const float4*>(x + (size_t)(row0 + r) * 784 + c4 * 4);
        }
        __syncthreads();
        const int j0 = jIdx * 8;
        ull axw[2][4] = {};
        for (int c = 0; c < 7; c++) {
            // stage W1T chunk [112][128]
            for (int idx = tid; idx < 112 * 32; idx += NTHR) {
                int kk = idx >> 5, j4 = idx & 31;
                *reinterpret_cast<float4*>(wch + kk * 128 + j4 * 4) =
                    *reinterpret_cast<const float4*>(g_W1T + (size_t)(c * 112 + kk) * 128 + j4 * 4);
            }
            __syncthreads();
            const float* a0 = xst + i0 * 784 + c * 112;
            const float* a1 = xst + (i0 + 1) * 784 + c * 112;
#pragma unroll 8
            for (int kk = 0; kk < 112; kk++) {
                const float* br = wch + kk * 128 + j0;
                ull b[4];
#pragma unroll
                for (int p = 0; p < 4; p++)
                    b[p] = *reinterpret_cast<const ull*>(br + 2 * p);
                ull A0 = dup2(a0[kk]), A1 = dup2(a1[kk]);
#pragma unroll
                for (int p = 0; p < 4; p++) {
                    fma2(axw[0][p], A0, b[p]);
                    fma2(axw[1][p], A1, b[p]);
                }
            }
            __syncthreads();
        }
#pragma unroll
        for (int p = 0; p < 4; p++) {
            float c0 = g_c1[j0 + 2 * p], c1v = g_c1[j0 + 2 * p + 1];
            float v0, v1;
            up2(axw[0][p], v0, v1);
            xwv[0][2 * p] = v0 + c0; xwv[0][2 * p + 1] = v1 + c1v;
            up2(axw[1][p], v0, v1);
            xwv[1][2 * p] = v0 + c0; xwv[1][2 * p + 1] = v1 + c1v;
        }
    }

    // load loop weights into smem (overwrites overlay)
    for (int idx = tid; idx < 4096; idx += NTHR)
        *reinterpret_cast<float4*>(sM1 + idx * 4) = *reinterpret_cast<const float4*>(g_M1T + idx * 4);
    for (int idx = tid; idx < 4096; idx += NTHR)
        *reinterpret_cast<float4*>(sU1 + idx * 4) = *reinterpret_cast<const float4*>(g_U1T + idx * 4);
    for (int idx = tid; idx < 2048; idx += NTHR)
        *reinterpret_cast<float4*>(sW2 + idx * 4) = *reinterpret_cast<const float4*>(g_W2T + idx * 4);
    for (int idx = tid; idx < 1024; idx += NTHR)
        *reinterpret_cast<float4*>(sM2 + idx * 4) = *reinterpret_cast<const float4*>(g_M2T + idx * 4);
    for (int idx = tid; idx < 1024; idx += NTHR)
        *reinterpret_cast<float4*>(sU2 + idx * 4) = *reinterpret_cast<const float4*>(g_U2T + idx * 4);

    // preload per-thread biases
    const int j1 = jIdx * 8, j2 = jIdx * 4, j3 = jIdx * 2;
    float U1bv[8], U2bv[4], c2v[4], U3bv[2], c3v[2];
#pragma unroll
    for (int c = 0; c < 8; c++) U1bv[c] = U1b[j1 + c];
#pragma unroll
    for (int c = 0; c < 4; c++) { U2bv[c] = U2b[j2 + c]; c2v[c] = g_c2[j2 + c]; }
#pragma unroll
    for (int c = 0; c < 2; c++) { U3bv[c] = U3b[j3 + c]; c3v[c] = g_c3[j3 + c]; }
    __syncthreads();

    // ---- step loop ----
    for (int s = 0; s < steps; s++) {
        ull aW3[2][1] = {}, aM3[2][1] = {}, aU3[2][1] = {};
        ull aW2[2][2] = {}, aM2[2][2] = {}, aU2[2][2] = {};
        ull aM1[2][4] = {}, aU1[2][4] = {};

        // L3 first: its global (L2-cache) b-loads overlap with L2/L1 smem compute
        gemm2<32, 1, 32, 32>(h3s, g_M3T, g_U3T, i0, j3, aM3, aU3);
        gemm1<64, 1, 32, 16>(h2s, g_W3T, i0, j3, aW3);
        // L2
        gemm2<64, 2, 64, 8>(h2s, sM2, sU2, i0, j2, aM2, aU2);
        gemm1<128, 2, 64, 8>(h1s, sW2, i0, j2, aW2);
        // L1 (dominant, all smem)
        gemm2<128, 4, 128, 8>(h1s, sM1, sU1, i0, j1, aM1, aU1);

        __syncthreads();

        // ---- updates (each element owned by exactly one thread) ----
        // L3
#pragma unroll
        for (int c = 0; c < 2; c++) {
            int j = j3 + c;
            float w0, w1, m0, m1, u0, u1;
            up2(aW3[0][0], w0, w1); up2(aM3[0][0], m0, m1); up2(aU3[0][0], u0, u1);
            float r0 = (c == 0) ? ftanh(w0 + m0 + c3v[0]) + ftanh(u0 + U3bv[0])
                                : ftanh(w1 + m1 + c3v[1]) + ftanh(u1 + U3bv[1]);
            up2(aW3[1][0], w0, w1); up2(aM3[1][0], m0, m1); up2(aU3[1][0], u0, u1);
            float r1 = (c == 0) ? ftanh(w0 + m0 + c3v[0]) + ftanh(u0 + U3bv[0])
                                : ftanh(w1 + m1 + c3v[1]) + ftanh(u1 + U3bv[1]);
            float2* hp = reinterpret_cast<float2*>(h3s + j * P + i0);
            float2 hv = *hp;
            hv.x += r0; hv.y += r1;
            *hp = hv;
        }
        // L2
#pragma unroll
        for (int p = 0; p < 2; p++) {
#pragma unroll
            for (int c = 0; c < 2; c++) {
                int cc = 2 * p + c;
                int j = j2 + cc;
                float w0, w1, m0, m1, u0, u1;
                up2(aW2[0][p], w0, w1); up2(aM2[0][p], m0, m1); up2(aU2[0][p], u0, u1);
                float r0 = (c == 0) ? ftanh(w0 + m0 + c2v[cc]) + ftanh(u0 + U2bv[cc])
                                    : ftanh(w1 + m1 + c2v[cc]) + ftanh(u1 + U2bv[cc]);
                up2(aW2[1][p], w0, w1); up2(aM2[1][p], m0, m1); up2(aU2[1][p], u0, u1);
                float r1 = (c == 0) ? ftanh(w0 + m0 + c2v[cc]) + ftanh(u0 + U2bv[cc])
                                    : ftanh(w1 + m1 + c2v[cc]) + ftanh(u1 + U2bv[cc]);
                float2* hp = reinterpret_cast<float2*>(h2s + j * P + i0);
                float2 hv = *hp;
                hv.x += r0; hv.y += r1;
                *hp = hv;
            }
        }
        // L1
#pragma unroll
        for (int p = 0; p < 4; p++) {
#pragma unroll
            for (int c = 0; c < 2; c++) {
                int cc = 2 * p + c;
                int j = j1 + cc;
                float m0, m1, u0, u1;
                up2(aM1[0][p], m0, m1); up2(aU1[0][p], u0, u1);
                float r0 = (c == 0) ? ftanh(xwv[0][cc] + m0) + ftanh(u0 + U1bv[cc])
                                    : ftanh(xwv[0][cc] + m1) + ftanh(u1 + U1bv[cc]);
                up2(aM1[1][p], m0, m1); up2(aU1[1][p], u0, u1);
                float r1 = (c == 0) ? ftanh(xwv[1][cc] + m0) + ftanh(u0 + U1bv[cc])
                                    : ftanh(xwv[1][cc] + m1) + ftanh(u1 + U1bv[cc]);
                float2* hp = reinterpret_cast<float2*>(h1s + j * P + i0);
                float2 hv = *hp;
                hv.x += r0; hv.y += r1;
                *hp = hv;
            }
        }
        __syncthreads();
    }

    // ---- classifier: out = h3 @ clf^T + clf_b ----
    for (int idx = tid; idx < BT * 10; idx += NTHR) {
        int r = idx / 10, cc = idx - r * 10;
        float sacc = clfb[cc];
#pragma unroll
        for (int k = 0; k < 32; k++) sacc += h3s[k * P + r] * clfw[cc * 32 + k];
        out[(size_t)(row0 + r) * 10 + cc] = sacc;
    }
}

// ---------------- launch ----------------
extern "C" void kernel_launch(void* const* d_in, const int* in_sizes, int n_in,
                              void* d_out, int out_size) {
    const float* x    = (const float*)d_in[0];
    const float* W1w  = (const float*)d_in[1];
    const float* W1b  = (const float*)d_in[2];
    const float* U1w  = (const float*)d_in[3];
    const float* U1b  = (const float*)d_in[4];
    const float* W2w  = (const float*)d_in[5];
    const float* W2b  = (const float*)d_in[6];
    const float* U2w  = (const float*)d_in[7];
    const float* U2b  = (const float*)d_in[8];
    const float* W3w  = (const float*)d_in[9];
    const float* W3b  = (const float*)d_in[10];
    const float* U3w  = (const float*)d_in[11];
    const float* U3b  = (const float*)d_in[12];
    const float* fb3w = (const float*)d_in[13];
    const float* fb3b = (const float*)d_in[14];
    const float* fb2w = (const float*)d_in[15];
    const float* fb2b = (const float*)d_in[16];
    const float* fb1w = (const float*)d_in[17];
    const float* fb1b = (const float*)d_in[18];
    const float* clfw = (const float*)d_in[19];
    const float* clfb = (const float*)d_in[20];
    const int*   stp  = (const int*)d_in[21];

    int B = in_sizes[0] / 784;

    prep_all<<<256, 128>>>(W1w, W1b, U1w, W2w, W2b, U2w, W3w, W3b, U3w,
                           fb3w, fb3b, fb2w, fb2b, fb1w, fb1b);

    const int smem_bytes = 56768 * 4;   // 227072
    cudaFuncSetAttribute(pcnet_main, cudaFuncAttributeMaxDynamicSharedMemorySize, smem_bytes);
    pcnet_main<<<B / BT, NTHR, smem_bytes>>>(x, U1b, U2b, U3b, clfw, clfb, stp, (float*)d_out);
}

// round 4
// speedup vs baseline: 1.9010x; 1.9010x over previous
#include <cuda_runtime.h>
#include <cstdint>

#define BT   64
#define P    68
#define NTHR 256
typedef unsigned long long ull;

// ---------------- persistent device scratch ----------------
__device__ __align__(16) float g_W1T[784*128];   // [k][j]
__device__ __align__(16) float g_M1T[128*128];   // -(W1@fb1)^T k-major
__device__ __align__(16) float g_U1T[128*128];
__device__ __align__(16) float g_W2T[128*64];
__device__ __align__(16) float g_M2T[64*64];     // negated
__device__ __align__(16) float g_U2T[64*64];
__device__ __align__(16) float g_L3W[4096];      // W3T[64*32] | -M3T[32*32] | U3T[32*32]
__device__ __align__(16) float g_c1[128];
__device__ __align__(16) float g_c2[64];
__device__ __align__(16) float g_c3[32];

// ---------------- helpers ----------------
__device__ __forceinline__ ull dup2(float x) {
    ull r; asm("mov.b64 %0, {%1, %1};" : "=l"(r) : "f"(x)); return r;
}
__device__ __forceinline__ void up2(ull v, float &lo, float &hi) {
    asm("mov.b64 {%0, %1}, %2;" : "=f"(lo), "=f"(hi) : "l"(v));
}
__device__ __forceinline__ void fma2(ull &d, ull a, ull b) {
    asm("fma.rn.f32x2 %0, %1, %2, %0;" : "+l"(d) : "l"(a), "l"(b));
}
// tanh(x) = 1 - 2/(1+e^{2x})  via MUFU.EX2 + MUFU.RCP (~1e-6 abs err)
__device__ __forceinline__ float ftanh(float x) {
    float e, r;
    asm("ex2.approx.ftz.f32 %0, %1;" : "=f"(e) : "f"(x * 2.8853900817779268f));
    asm("rcp.approx.ftz.f32 %0, %1;" : "=f"(r) : "f"(e + 1.0f));
    return fmaf(-2.0f, r, 1.0f);
}

// single-B GEMM: A feature-major [K][P] smem, B k-major [K][LDB] smem.
// thread: 4 rows (i0..i0+3) x NC ull-columns at offsets jo[]
template<int K, int LDB, int NC, int UNR>
__device__ __forceinline__ void gemmS(const float* __restrict__ A, const float* __restrict__ B,
                                      int i0, const int (&jo)[NC], ull (&acc)[4][NC]) {
#pragma unroll UNR
    for (int k = 0; k < K; k++) {
        float4 a4 = *reinterpret_cast<const float4*>(A + k * P + i0);
        ull b[NC];
#pragma unroll
        for (int c = 0; c < NC; c++)
            b[c] = *reinterpret_cast<const ull*>(B + k * LDB + jo[c]);
        ull A0 = dup2(a4.x), A1 = dup2(a4.y), A2 = dup2(a4.z), A3 = dup2(a4.w);
#pragma unroll
        for (int c = 0; c < NC; c++) {
            fma2(acc[0][c], A0, b[c]);
            fma2(acc[1][c], A1, b[c]);
            fma2(acc[2][c], A2, b[c]);
            fma2(acc[3][c], A3, b[c]);
        }
    }
}

// L1 dual GEMM: shared A, B1/B2 [128][128]; cols {j4..j4+3} and {64+j4..64+j4+3}
__device__ __forceinline__ void gemmL1(const float* __restrict__ A, const float* __restrict__ B1,
                                       const float* __restrict__ B2, int i0, int j4,
                                       ull (&m)[4][4], ull (&u)[4][4]) {
#pragma unroll 4
    for (int k = 0; k < 128; k++) {
        float4 a4 = *reinterpret_cast<const float4*>(A + k * P + i0);
        ulonglong2 bm0 = *reinterpret_cast<const ulonglong2*>(B1 + k * 128 + j4);
        ulonglong2 bm1 = *reinterpret_cast<const ulonglong2*>(B1 + k * 128 + 64 + j4);
        ulonglong2 bu0 = *reinterpret_cast<const ulonglong2*>(B2 + k * 128 + j4);
        ulonglong2 bu1 = *reinterpret_cast<const ulonglong2*>(B2 + k * 128 + 64 + j4);
        ull A0 = dup2(a4.x), A1 = dup2(a4.y), A2 = dup2(a4.z), A3 = dup2(a4.w);
        ull Ar[4] = {A0, A1, A2, A3};
#pragma unroll
        for (int r = 0; r < 4; r++) {
            fma2(m[r][0], Ar[r], bm0.x);
            fma2(m[r][1], Ar[r], bm0.y);
            fma2(m[r][2], Ar[r], bm1.x);
            fma2(m[r][3], Ar[r], bm1.y);
            fma2(u[r][0], Ar[r], bu0.x);
            fma2(u[r][1], Ar[r], bu0.y);
            fma2(u[r][2], Ar[r], bu1.x);
            fma2(u[r][3], Ar[r], bu1.y);
        }
    }
}

// panel stage: 4096 floats, 4 float4 per thread
__device__ __forceinline__ void ldg_panel(const float* __restrict__ src, int tid, float4 (&r)[4]) {
#pragma unroll
    for (int j = 0; j < 4; j++)
        r[j] = *reinterpret_cast<const float4*>(src + (j * 256 + tid) * 4);
}
__device__ __forceinline__ void sts_panel(float* dst, int tid, const float4 (&r)[4]) {
#pragma unroll
    for (int j = 0; j < 4; j++)
        *reinterpret_cast<float4*>(dst + (j * 256 + tid) * 4) = r[j];
}

// ---------------- prep kernel ----------------
__global__ void prep_all(const float* __restrict__ W1w, const float* __restrict__ W1b,
                         const float* __restrict__ U1w,
                         const float* __restrict__ W2w, const float* __restrict__ W2b,
                         const float* __restrict__ U2w,
                         const float* __restrict__ W3w, const float* __restrict__ W3b,
                         const float* __restrict__ U3w,
                         const float* __restrict__ fb3w, const float* __restrict__ fb3b,
                         const float* __restrict__ fb2w, const float* __restrict__ fb2b,
                         const float* __restrict__ fb1w, const float* __restrict__ fb1b) {
    __shared__ float row_s[784];
    __shared__ float red_s[128];
    const int bid = blockIdx.x;
    const int tid = threadIdx.x;   // 128

    if (bid < 128) {
        const int j = bid;
        for (int d = tid; d < 784; d += 128) row_s[d] = W1w[j * 784 + d];
        __syncthreads();
        {
            const int k = tid;
            float s = 0.f;
#pragma unroll 4
            for (int d = 0; d < 784; d++) s += row_s[d] * fb1w[d * 128 + k];
            g_M1T[k * 128 + j] = -s;
        }
        float ps = 0.f;
        for (int d = tid; d < 784; d += 128) ps += row_s[d] * fb1b[d];
        red_s[tid] = ps;
        __syncthreads();
        for (int off = 64; off > 0; off >>= 1) {
            if (tid < off) red_s[tid] += red_s[tid + off];
            __syncthreads();
        }
        if (tid == 0) g_c1[j] = W1b[j] - red_s[0];
    } else if (bid < 192) {
        const int j = bid - 128;
        for (int d = tid; d < 128; d += 128) row_s[d] = W2w[j * 128 + d];
        __syncthreads();
        if (tid < 64) {
            const int k = tid;
            float s = 0.f;
#pragma unroll 4
            for (int d = 0; d < 128; d++) s += row_s[d] * fb2w[d * 64 + k];
            g_M2T[k * 64 + j] = -s;
        }
        float ps = 0.f;
        for (int d = tid; d < 128; d += 128) ps += row_s[d] * fb2b[d];
        red_s[tid] = ps;
        __syncthreads();
        for (int off = 64; off > 0; off >>= 1) {
            if (tid < off) red_s[tid] += red_s[tid + off];
            __syncthreads();
        }
        if (tid == 0) g_c2[j] = W2b[j] - red_s[0];
    } else if (bid < 224) {
        const int j = bid - 192;
        for (int d = tid; d < 64; d += 128) row_s[d] = W3w[j * 64 + d];
        __syncthreads();
        if (tid < 32) {
            const int k = tid;
            float s = 0.f;
#pragma unroll 4
            for (int d = 0; d < 64; d++) s += row_s[d] * fb3w[d * 32 + k];
            g_L3W[2048 + k * 32 + j] = -s;    // -M3T
        }
        float ps = 0.f;
        for (int d = tid; d < 64; d += 128) ps += row_s[d] * fb3b[d];
        red_s[tid] = ps;
        __syncthreads();
        for (int off = 64; off > 0; off >>= 1) {
            if (tid < off) red_s[tid] += red_s[tid + off];
            __syncthreads();
        }
        if (tid == 0) g_c3[j] = W3b[j] - red_s[0];
    } else {
        const int idx0 = (bid - 224) * 128 + tid;
        const int stride = 32 * 128;
        for (int t = idx0; t < 784 * 128; t += stride) {
            int k = t >> 7, j = t & 127;
            g_W1T[t] = W1w[j * 784 + k];
        }
        for (int t = idx0; t < 128 * 128; t += stride) {
            int k = t >> 7, j = t & 127;
            g_U1T[t] = U1w[j * 128 + k];
        }
        for (int t = idx0; t < 128 * 64; t += stride) {
            int k = t >> 6, j = t & 63;
            g_W2T[t] = W2w[j * 128 + k];
        }
        for (int t = idx0; t < 64 * 64; t += stride) {
            int k = t >> 6, j = t & 63;
            g_U2T[t] = U2w[j * 64 + k];
        }
        for (int t = idx0; t < 64 * 32; t += stride) {          // W3T
            int k = t >> 5, j = t & 31;
            g_L3W[t] = W3w[j * 64 + k];
        }
        for (int t = idx0; t < 32 * 32; t += stride) {          // U3T
            int k = t >> 5, j = t & 31;
            g_L3W[3072 + t] = U3w[j * 32 + k];
        }
    }
}

// ---------------- main kernel ----------------
// smem floats: h1s[128*68]@0, h2s[64*68]@8704, h3s[32*68]@13056,
//   sM1@15232(16384), sU1@31616(16384), buf0@48000(4096), buf1@52096(4096)
// total 56192 fl = 224768 B.  Phase-1 overlay: xck@0 [64][116], wck@7424 [112][128]
__global__ void __launch_bounds__(NTHR, 1)
pcnet_main(const float* __restrict__ x,
           const float* __restrict__ U1b, const float* __restrict__ U2b,
           const float* __restrict__ U3b,
           const float* __restrict__ clfw, const float* __restrict__ clfb,
           const int* __restrict__ steps_p,
           float* __restrict__ out) {
    extern __shared__ float sm[];
    float* h1s = sm;
    float* h2s = sm + 8704;
    float* h3s = sm + 13056;
    float* sM1 = sm + 15232;
    float* sU1 = sm + 31616;
    float* bufs0 = sm + 48000;
    float* bufs1 = sm + 52096;
    float* xck = sm;            // overlay
    float* wck = sm + 7424;     // overlay

    const int tid  = threadIdx.x;
    const int row0 = blockIdx.x * BT;
    const int rg = tid >> 4;          // 0..15
    const int cg = tid & 15;          // 0..15
    const int i0 = rg * 4;
    const int j4 = cg * 4;

    int steps = *steps_p;
    if (steps < 0 || steps > 64) steps = 5;

    // ---- phase 1: xw = x @ W1^T + c1 (kept in regs) ----
    float xwf[4][8];
    {
        ull axw[4][4] = {};
        for (int c = 0; c < 7; c++) {
            // stage x chunk [64 rows][112 k] pitch 116
            for (int idx = tid; idx < 64 * 28; idx += NTHR) {
                int r = idx / 28, k4 = idx - r * 28;
                *reinterpret_cast<float4*>(xck + r * 116 + k4 * 4) =
                    *reinterpret_cast<const float4*>(x + (size_t)(row0 + r) * 784 + c * 112 + k4 * 4);
            }
            // stage W1T chunk [112][128]
            for (int idx = tid; idx < 112 * 32; idx += NTHR) {
                int kk = idx >> 5, jj = idx & 31;
                *reinterpret_cast<float4*>(wck + kk * 128 + jj * 4) =
                    *reinterpret_cast<const float4*>(g_W1T + (size_t)(c * 112 + kk) * 128 + jj * 4);
            }
            __syncthreads();
#pragma unroll 2
            for (int kk = 0; kk < 112; kk++) {
                ulonglong2 b0 = *reinterpret_cast<const ulonglong2*>(wck + kk * 128 + j4);
                ulonglong2 b1 = *reinterpret_cast<const ulonglong2*>(wck + kk * 128 + 64 + j4);
                ull A0 = dup2(xck[(i0 + 0) * 116 + kk]);
                ull A1 = dup2(xck[(i0 + 1) * 116 + kk]);
                ull A2 = dup2(xck[(i0 + 2) * 116 + kk]);
                ull A3 = dup2(xck[(i0 + 3) * 116 + kk]);
                ull Ar[4] = {A0, A1, A2, A3};
#pragma unroll
                for (int r = 0; r < 4; r++) {
                    fma2(axw[r][0], Ar[r], b0.x);
                    fma2(axw[r][1], Ar[r], b0.y);
                    fma2(axw[r][2], Ar[r], b1.x);
                    fma2(axw[r][3], Ar[r], b1.y);
                }
            }
            __syncthreads();
        }
        // add c1, unpack (cols: cc<4 -> 4cg+cc ; cc>=4 -> 64+4cg+cc-4)
        float c1v[8];
#pragma unroll
        for (int t = 0; t < 4; t++) { c1v[t] = g_c1[j4 + t]; c1v[4 + t] = g_c1[64 + j4 + t]; }
#pragma unroll
        for (int r = 0; r < 4; r++) {
#pragma unroll
            for (int c = 0; c < 4; c++) {
                float lo, hi;
                up2(axw[r][c], lo, hi);
                xwf[r][2 * c]     = lo + c1v[2 * c];
                xwf[r][2 * c + 1] = hi + c1v[2 * c + 1];
            }
        }
    }

    // zero states, load resident weights, stage first L3 panel
    for (int i = tid; i < 15232; i += NTHR) sm[i] = 0.f;
    for (int idx = tid; idx < 4096; idx += NTHR)
        *reinterpret_cast<float4*>(sM1 + idx * 4) = *reinterpret_cast<const float4*>(g_M1T + idx * 4);
    for (int idx = tid; idx < 4096; idx += NTHR)
        *reinterpret_cast<float4*>(sU1 + idx * 4) = *reinterpret_cast<const float4*>(g_U1T + idx * 4);
    for (int idx = tid; idx < 1024; idx += NTHR)
        *reinterpret_cast<float4*>(bufs0 + idx * 4) = *reinterpret_cast<const float4*>(g_L3W + idx * 4);

    // biases
    const int joL3[1] = {2 * cg};
    const int joL2[2] = {2 * cg, 32 + 2 * cg};
    float c3v[2], U3bv[2], c2v[4], U2bv[4], U1bv[8];
#pragma unroll
    for (int d = 0; d < 2; d++) { c3v[d] = g_c3[2 * cg + d]; U3bv[d] = U3b[2 * cg + d]; }
#pragma unroll
    for (int p = 0; p < 2; p++) {
#pragma unroll
        for (int d = 0; d < 2; d++) {
            c2v[2 * p + d]  = g_c2[joL2[p] + d];
            U2bv[2 * p + d] = U2b[joL2[p] + d];
        }
    }
#pragma unroll
    for (int t = 0; t < 4; t++) { U1bv[t] = U1b[j4 + t]; U1bv[4 + t] = U1b[64 + j4 + t]; }
    __syncthreads();

    int pb = 0;
    for (int s = 0; s < steps; s++) {
        float* bw = pb ? bufs1 : bufs0;   // currently holds L3 weights
        float* bo = pb ? bufs0 : bufs1;
        float4 pr[4];

        // --- phase A: L3 + L2 gemms with panel streaming ---
        ull aW3[4][1] = {}, aM3[4][1] = {}, aU3[4][1] = {};
        ldg_panel(g_W2T, tid, pr);                       // W2a
        gemmS<64, 32, 1, 8>(h2s, bw, i0, joL3, aW3);
        gemmS<32, 32, 1, 16>(h3s, bw + 2048, i0, joL3, aM3);
        gemmS<32, 32, 1, 16>(h3s, bw + 3072, i0, joL3, aU3);
        sts_panel(bo, tid, pr);
        __syncthreads();

        ull aW2[4][2] = {};
        ldg_panel(g_W2T + 4096, tid, pr);                // W2b
        gemmS<64, 64, 2, 8>(h1s, bo, i0, joL2, aW2);
        sts_panel(bw, tid, pr);
        __syncthreads();

        ldg_panel(g_M2T, tid, pr);
        gemmS<64, 64, 2, 8>(h1s + 64 * P, bw, i0, joL2, aW2);
        sts_panel(bo, tid, pr);
        __syncthreads();

        ull aM2[4][2] = {};
        ldg_panel(g_U2T, tid, pr);
        gemmS<64, 64, 2, 8>(h2s, bo, i0, joL2, aM2);
        sts_panel(bw, tid, pr);
        __syncthreads();

        ull aU2[4][2] = {};
        ldg_panel(g_L3W, tid, pr);                       // next step's L3 panel
        gemmS<64, 64, 2, 8>(h2s, bw, i0, joL2, aU2);
        sts_panel(bo, tid, pr);
        __syncthreads();

        // --- update h3, h2 (all reads of h2s/h3s are complete) ---
#pragma unroll
        for (int r = 0; r < 4; r++) {
            float w0, w1, m0, m1, u0, u1;
            up2(aW3[r][0], w0, w1);
            up2(aM3[r][0], m0, m1);
            up2(aU3[r][0], u0, u1);
            h3s[(2 * cg) * P + i0 + r]     += ftanh(w0 + m0 + c3v[0]) + ftanh(u0 + U3bv[0]);
            h3s[(2 * cg + 1) * P + i0 + r] += ftanh(w1 + m1 + c3v[1]) + ftanh(u1 + U3bv[1]);
        }
#pragma unroll
        for (int p = 0; p < 2; p++) {
#pragma unroll
            for (int r = 0; r < 4; r++) {
                float w0, w1, m0, m1, u0, u1;
                up2(aW2[r][p], w0, w1);
                up2(aM2[r][p], m0, m1);
                up2(aU2[r][p], u0, u1);
                h2s[(joL2[p]) * P + i0 + r]     += ftanh(w0 + m0 + c2v[2 * p]) + ftanh(u0 + U2bv[2 * p]);
                h2s[(joL2[p] + 1) * P + i0 + r] += ftanh(w1 + m1 + c2v[2 * p + 1]) + ftanh(u1 + U2bv[2 * p + 1]);
            }
        }

        // --- L1 dual gemm (reads h1s only; safe to overlap with h2/h3 updates) ---
        ull aM1[4][4] = {}, aU1[4][4] = {};
        gemmL1(h1s, sM1, sU1, i0, j4, aM1, aU1);
        __syncthreads();   // all h1s reads done

        // --- update h1 ---
#pragma unroll
        for (int c = 0; c < 4; c++) {
            int base = (c < 2) ? (j4 + 2 * c) : (60 + j4 + 2 * c);
#pragma unroll
            for (int r = 0; r < 4; r++) {
                float m0, m1, u0, u1;
                up2(aM1[r][c], m0, m1);
                up2(aU1[r][c], u0, u1);
                h1s[base * P + i0 + r]       += ftanh(xwf[r][2 * c] + m0)     + ftanh(u0 + U1bv[2 * c]);
                h1s[(base + 1) * P + i0 + r] += ftanh(xwf[r][2 * c + 1] + m1) + ftanh(u1 + U1bv[2 * c + 1]);
            }
        }
        __syncthreads();
        pb ^= 1;
    }

    // ---- classifier: out = h3 @ clf^T + clf_b ----
    for (int idx = tid; idx < BT * 10; idx += NTHR) {
        int r = idx / 10, cc = idx - r * 10;
        float sacc = clfb[cc];
#pragma unroll
        for (int k = 0; k < 32; k++) sacc += h3s[k * P + r] * clfw[cc * 32 + k];
        out[(size_t)(row0 + r) * 10 + cc] = sacc;
    }
}

// ---------------- launch ----------------
extern "C" void kernel_launch(void* const* d_in, const int* in_sizes, int n_in,
                              void* d_out, int out_size) {
    const float* x    = (const float*)d_in[0];
    const float* W1w  = (const float*)d_in[1];
    const float* W1b  = (const float*)d_in[2];
    const float* U1w  = (const float*)d_in[3];
    const float* U1b  = (const float*)d_in[4];
    const float* W2w  = (const float*)d_in[5];
    const float* W2b  = (const float*)d_in[6];
    const float* U2w  = (const float*)d_in[7];
    const float* U2b  = (const float*)d_in[8];
    const float* W3w  = (const float*)d_in[9];
    const float* W3b  = (const float*)d_in[10];
    const float* U3w  = (const float*)d_in[11];
    const float* U3b  = (const float*)d_in[12];
    const float* fb3w = (const float*)d_in[13];
    const float* fb3b = (const float*)d_in[14];
    const float* fb2w = (const float*)d_in[15];
    const float* fb2b = (const float*)d_in[16];
    const float* fb1w = (const float*)d_in[17];
    const float* fb1b = (const float*)d_in[18];
    const float* clfw = (const float*)d_in[19];
    const float* clfb = (const float*)d_in[20];
    const int*   stp  = (const int*)d_in[21];

    int B = in_sizes[0] / 784;

    prep_all<<<256, 128>>>(W1w, W1b, U1w, W2w, W2b, U2w, W3w, W3b, U3w,
                           fb3w, fb3b, fb2w, fb2b, fb1w, fb1b);

    const int smem_bytes = 56192 * 4;   // 224768
    cudaFuncSetAttribute(pcnet_main, cudaFuncAttributeMaxDynamicSharedMemorySize, smem_bytes);
    pcnet_main<<<B / BT, NTHR, smem_bytes>>>(x, U1b, U2b, U3b, clfw, clfb, stp, (float*)d_out);
}

// round 6
// speedup vs baseline: 2.3498x; 1.2361x over previous
#include <cuda_runtime.h>
#include <cstdint>

#define BT   64
#define P    68
#define NTHR 256
typedef unsigned long long ull;

// ---------------- persistent device scratch ----------------
__device__ __align__(16) float g_W1T[784*128];   // [k][j]
__device__ __align__(16) float g_L1P[32768];     // 16 pairs: [8][128] -M1T | [8][128] U1T
__device__ __align__(16) float g_W2T[128*64];
__device__ __align__(16) float g_M2T[64*64];     // negated
__device__ __align__(16) float g_U2T[64*64];
__device__ __align__(16) float g_L3P[4096];      // W3T[64*32] | -M3T[32*32] | U3T[32*32]
__device__ __align__(16) float g_c1[128];
__device__ __align__(16) float g_c2[64];
__device__ __align__(16) float g_c3[32];

// ---------------- helpers ----------------
__device__ __forceinline__ ull dup2(float x) {
    ull r; asm("mov.b64 %0, {%1, %1};" : "=l"(r) : "f"(x)); return r;
}
__device__ __forceinline__ void up2(ull v, float &lo, float &hi) {
    asm("mov.b64 {%0, %1}, %2;" : "=f"(lo), "=f"(hi) : "l"(v));
}
__device__ __forceinline__ void fma2(ull &d, ull a, ull b) {
    asm("fma.rn.f32x2 %0, %1, %2, %0;" : "+l"(d) : "l"(a), "l"(b));
}
// tanh(x) = 1 - 2/(1+e^{2x})  via MUFU.EX2 + MUFU.RCP (~1e-6 abs err)
__device__ __forceinline__ float ftanh(float x) {
    float e, r;
    asm("ex2.approx.ftz.f32 %0, %1;" : "=f"(e) : "f"(x * 2.8853900817779268f));
    asm("rcp.approx.ftz.f32 %0, %1;" : "=f"(r) : "f"(e + 1.0f));
    return fmaf(-2.0f, r, 1.0f);
}
__device__ __forceinline__ void addf4(float4 &v, int r, float d) {
    if (r == 0) v.x += d; else if (r == 1) v.y += d;
    else if (r == 2) v.z += d; else v.w += d;
}

// single-B GEMM: A feature-major [K][P] smem, B k-major [K][LDB] smem panel
template<int K, int LDB, int NC, int UNR>
__device__ __forceinline__ void gemmS(const float* __restrict__ A, const float* __restrict__ B,
                                      int i0, const int (&jo)[NC], ull (&acc)[4][NC]) {
#pragma unroll UNR
    for (int k = 0; k < K; k++) {
        float4 a4 = *reinterpret_cast<const float4*>(A + k * P + i0);
        ull b[NC];
#pragma unroll
        for (int c = 0; c < NC; c++)
            b[c] = *reinterpret_cast<const ull*>(B + k * LDB + jo[c]);
        ull Ar[4] = {dup2(a4.x), dup2(a4.y), dup2(a4.z), dup2(a4.w)};
#pragma unroll
        for (int c = 0; c < NC; c++) {
#pragma unroll
            for (int r = 0; r < 4; r++) fma2(acc[r][c], Ar[r], b[c]);
        }
    }
}

// L1 paired dual GEMM, K=8 chunk: Bm = -M1T rows, Bu = U1T rows (both [8][128])
__device__ __forceinline__ void gemmP(const float* __restrict__ A, const float* __restrict__ Bm,
                                      const float* __restrict__ Bu, int i0, int j4,
                                      ull (&m)[4][4], ull (&u)[4][4]) {
#pragma unroll
    for (int k = 0; k < 8; k++) {
        float4 a4 = *reinterpret_cast<const float4*>(A + k * P + i0);
        ulonglong2 bm0 = *reinterpret_cast<const ulonglong2*>(Bm + k * 128 + j4);
        ulonglong2 bm1 = *reinterpret_cast<const ulonglong2*>(Bm + k * 128 + 64 + j4);
        ulonglong2 bu0 = *reinterpret_cast<const ulonglong2*>(Bu + k * 128 + j4);
        ulonglong2 bu1 = *reinterpret_cast<const ulonglong2*>(Bu + k * 128 + 64 + j4);
        ull Ar[4] = {dup2(a4.x), dup2(a4.y), dup2(a4.z), dup2(a4.w)};
#pragma unroll
        for (int r = 0; r < 4; r++) {
            fma2(m[r][0], Ar[r], bm0.x);
            fma2(m[r][1], Ar[r], bm0.y);
            fma2(m[r][2], Ar[r], bm1.x);
            fma2(m[r][3], Ar[r], bm1.y);
            fma2(u[r][0], Ar[r], bu0.x);
            fma2(u[r][1], Ar[r], bu0.y);
            fma2(u[r][2], Ar[r], bu1.x);
            fma2(u[r][3], Ar[r], bu1.y);
        }
    }
}

// 2048-float panel staging: 2 float4 per thread  (halves at +0 and +1024 floats)
__device__ __forceinline__ void pld(const float* __restrict__ src, int tid, float4 (&r)[2]) {
    r[0] = *reinterpret_cast<const float4*>(src + tid * 4);
    r[1] = *reinterpret_cast<const float4*>(src + 1024 + tid * 4);
}
__device__ __forceinline__ void pst(float* dst, int tid, const float4 (&r)[2]) {
    *reinterpret_cast<float4*>(dst + tid * 4) = r[0];
    *reinterpret_cast<float4*>(dst + 1024 + tid * 4) = r[1];
}

// ---------------- prep kernel ----------------
__global__ void prep_all(const float* __restrict__ W1w, const float* __restrict__ W1b,
                         const float* __restrict__ U1w,
                         const float* __restrict__ W2w, const float* __restrict__ W2b,
                         const float* __restrict__ U2w,
                         const float* __restrict__ W3w, const float* __restrict__ W3b,
                         const float* __restrict__ U3w,
                         const float* __restrict__ fb3w, const float* __restrict__ fb3b,
                         const float* __restrict__ fb2w, const float* __restrict__ fb2b,
                         const float* __restrict__ fb1w, const float* __restrict__ fb1b) {
    __shared__ float row_s[784];
    __shared__ float red_s[128];
    const int bid = blockIdx.x;
    const int tid = threadIdx.x;   // 128

    if (bid < 128) {
        const int j = bid;
        for (int d = tid; d < 784; d += 128) row_s[d] = W1w[j * 784 + d];
        __syncthreads();
        {
            const int k = tid;
            float s = 0.f;
#pragma unroll 4
            for (int d = 0; d < 784; d++) s += row_s[d] * fb1w[d * 128 + k];
            g_L1P[(k >> 3) * 2048 + (k & 7) * 128 + j] = -s;   // -M1T pair layout
        }
        float ps = 0.f;
        for (int d = tid; d < 784; d += 128) ps += row_s[d] * fb1b[d];
        red_s[tid] = ps;
        __syncthreads();
        for (int off = 64; off > 0; off >>= 1) {
            if (tid < off) red_s[tid] += red_s[tid + off];
            __syncthreads();
        }
        if (tid == 0) g_c1[j] = W1b[j] - red_s[0];
    } else if (bid < 192) {
        const int j = bid - 128;
        for (int d = tid; d < 128; d += 128) row_s[d] = W2w[j * 128 + d];
        __syncthreads();
        if (tid < 64) {
            const int k = tid;
            float s = 0.f;
#pragma unroll 4
            for (int d = 0; d < 128; d++) s += row_s[d] * fb2w[d * 64 + k];
            g_M2T[k * 64 + j] = -s;
        }
        float ps = 0.f;
        for (int d = tid; d < 128; d += 128) ps += row_s[d] * fb2b[d];
        red_s[tid] = ps;
        __syncthreads();
        for (int off = 64; off > 0; off >>= 1) {
            if (tid < off) red_s[tid] += red_s[tid + off];
            __syncthreads();
        }
        if (tid == 0) g_c2[j] = W2b[j] - red_s[0];
    } else if (bid < 224) {
        const int j = bid - 192;
        for (int d = tid; d < 64; d += 128) row_s[d] = W3w[j * 64 + d];
        __syncthreads();
        if (tid < 32) {
            const int k = tid;
            float s = 0.f;
#pragma unroll 4
            for (int d = 0; d < 64; d++) s += row_s[d] * fb3w[d * 32 + k];
            g_L3P[2048 + k * 32 + j] = -s;    // -M3T
        }
        float ps = 0.f;
        for (int d = tid; d < 64; d += 128) ps += row_s[d] * fb3b[d];
        red_s[tid] = ps;
        __syncthreads();
        for (int off = 64; off > 0; off >>= 1) {
            if (tid < off) red_s[tid] += red_s[tid + off];
            __syncthreads();
        }
        if (tid == 0) g_c3[j] = W3b[j] - red_s[0];
    } else {
        const int idx0 = (bid - 224) * 128 + tid;
        const int stride = 32 * 128;
        for (int t = idx0; t < 784 * 128; t += stride) {
            int k = t >> 7, j = t & 127;
            g_W1T[t] = W1w[j * 784 + k];
        }
        for (int t = idx0; t < 128 * 128; t += stride) {          // U1T pair layout
            int k = t >> 7, j = t & 127;
            g_L1P[(k >> 3) * 2048 + 1024 + (k & 7) * 128 + j] = U1w[j * 128 + k];
        }
        for (int t = idx0; t < 128 * 64; t += stride) {
            int k = t >> 6, j = t & 63;
            g_W2T[t] = W2w[j * 128 + k];
        }
        for (int t = idx0; t < 64 * 64; t += stride) {
            int k = t >> 6, j = t & 63;
            g_U2T[t] = U2w[j * 64 + k];
        }
        for (int t = idx0; t < 64 * 32; t += stride) {            // W3T
            int k = t >> 5, j = t & 31;
            g_L3P[t] = W3w[j * 64 + k];
        }
        for (int t = idx0; t < 32 * 32; t += stride) {            // U3T
            int k = t >> 5, j = t & 31;
            g_L3P[3072 + t] = U3w[j * 32 + k];
        }
    }
}

// ---------------- main kernel ----------------
// smem floats (27840 total = 111360 B, 2 CTAs/SM):
//   h1s[128*68]@0  h2s[64*68]@8704  h3s[32*68]@13056
//   xws[64][128]@15232 (8192)  buf0@23424(2048)  buf1@25472(2048)  sB@27520(320)
// phase-1 overlay: xck@0 [64][116]=7424, wck@7424 [112][128]=14336 (ends 21760 < buf0)
__global__ void __launch_bounds__(NTHR, 2)
pcnet_main(const float* __restrict__ x,
           const float* __restrict__ U1b, const float* __restrict__ U2b,
           const float* __restrict__ U3b,
           const float* __restrict__ clfw, const float* __restrict__ clfb,
           const int* __restrict__ steps_p,
           float* __restrict__ out) {
    extern __shared__ float sm[];
    float* h1s  = sm;
    float* h2s  = sm + 8704;
    float* h3s  = sm + 13056;
    float* xws  = sm + 15232;
    float* buf0 = sm + 23424;
    float* buf1 = sm + 25472;
    float* sB   = sm + 27520;
    float* xck  = sm;           // overlay
    float* wck  = sm + 7424;    // overlay

    const int tid  = threadIdx.x;
    const int row0 = blockIdx.x * BT;
    const int rg = tid >> 4;
    const int cg = tid & 15;
    const int i0 = rg * 4;
    const int j4 = cg * 4;

    int steps = *steps_p;
    if (steps < 0 || steps > 64) steps = 5;

    // stage biases + first panel (regions disjoint from phase-1 overlay)
    for (int t = tid; t < 320; t += NTHR) {
        float v;
        if (t < 32) v = g_c3[t];
        else if (t < 64) v = U3b[t - 32];
        else if (t < 128) v = g_c2[t - 64];
        else if (t < 192) v = U2b[t - 128];
        else v = U1b[t - 192];
        sB[t] = v;
    }
    for (int idx = tid; idx < 512; idx += NTHR)
        *reinterpret_cast<float4*>(buf0 + idx * 4) = *reinterpret_cast<const float4*>(g_L3P + idx * 4);

    // ---- phase 1: xw = x @ W1^T + c1 -> xws ----
    {
        ull axw[4][4] = {};
        for (int c = 0; c < 7; c++) {
            for (int idx = tid; idx < 64 * 28; idx += NTHR) {
                int r = idx / 28, k4 = idx - r * 28;
                *reinterpret_cast<float4*>(xck + r * 116 + k4 * 4) =
                    *reinterpret_cast<const float4*>(x + (size_t)(row0 + r) * 784 + c * 112 + k4 * 4);
            }
            for (int idx = tid; idx < 112 * 32; idx += NTHR) {
                int kk = idx >> 5, jj = idx & 31;
                *reinterpret_cast<float4*>(wck + kk * 128 + jj * 4) =
                    *reinterpret_cast<const float4*>(g_W1T + (size_t)(c * 112 + kk) * 128 + jj * 4);
            }
            __syncthreads();
#pragma unroll 2
            for (int kk = 0; kk < 112; kk++) {
                ulonglong2 b0 = *reinterpret_cast<const ulonglong2*>(wck + kk * 128 + j4);
                ulonglong2 b1 = *reinterpret_cast<const ulonglong2*>(wck + kk * 128 + 64 + j4);
                ull Ar[4] = {dup2(xck[(i0 + 0) * 116 + kk]), dup2(xck[(i0 + 1) * 116 + kk]),
                             dup2(xck[(i0 + 2) * 116 + kk]), dup2(xck[(i0 + 3) * 116 + kk])};
#pragma unroll
                for (int r = 0; r < 4; r++) {
                    fma2(axw[r][0], Ar[r], b0.x);
                    fma2(axw[r][1], Ar[r], b0.y);
                    fma2(axw[r][2], Ar[r], b1.x);
                    fma2(axw[r][3], Ar[r], b1.y);
                }
            }
            __syncthreads();
        }
        // write xw (+c1) into xws [row][feat]
        float c1v[8];
#pragma unroll
        for (int t = 0; t < 4; t++) { c1v[t] = g_c1[j4 + t]; c1v[4 + t] = g_c1[64 + j4 + t]; }
#pragma unroll
        for (int r = 0; r < 4; r++) {
#pragma unroll
            for (int c = 0; c < 4; c++) {
                int col = (c < 2) ? (j4 + 2 * c) : (60 + j4 + 2 * c);
                float lo, hi;
                up2(axw[r][c], lo, hi);
                xws[(i0 + r) * 128 + col]     = lo + c1v[2 * c];
                xws[(i0 + r) * 128 + col + 1] = hi + c1v[2 * c + 1];
            }
        }
    }
    // zero states (overlays xck region; xws/buf/sB untouched)
    for (int i = tid; i < 15232; i += NTHR) sm[i] = 0.f;
    __syncthreads();

    const int joL3[1] = {2 * cg};
    const int joL2[2] = {2 * cg, 32 + 2 * cg};
    float* cur = buf0;
    float* oth = buf1;

    // ---- step loop: 26 panel slots/step ----
    for (int s = 0; s < steps; s++) {
        float4 pr[2];
        ull aW3[4][1] = {}, aM3[4][1] = {}, aU3[4][1] = {};

        // slot 0: W3 (panel = W3T [64][32])
        pld(g_L3P + 2048, tid, pr);
        gemmS<64, 32, 1, 8>(h2s, cur, i0, joL3, aW3);
        pst(oth, tid, pr); __syncthreads();
        { float* t = cur; cur = oth; oth = t; }

        // slot 1: M3|U3 (panel = [-M3T | U3T], 1024 each)
        pld(g_W2T, tid, pr);
        gemmS<32, 32, 1, 8>(h3s, cur, i0, joL3, aM3);
        gemmS<32, 32, 1, 8>(h3s, cur + 1024, i0, joL3, aU3);
        pst(oth, tid, pr); __syncthreads();
        { float* t = cur; cur = oth; oth = t; }

        // slots 2-5: W2 (4 chunks of 32 k)
        ull aW2[4][2] = {};
#pragma unroll
        for (int p = 0; p < 4; p++) {
            const float* nx = (p < 3) ? (g_W2T + (p + 1) * 2048) : g_M2T;
            pld(nx, tid, pr);
            gemmS<32, 64, 2, 8>(h1s + 32 * p * P, cur, i0, joL2, aW2);
            pst(oth, tid, pr); __syncthreads();
            float* t = cur; cur = oth; oth = t;
        }
        // slots 6-7: M2
        ull aM2[4][2] = {};
#pragma unroll
        for (int p = 0; p < 2; p++) {
            const float* nx = p ? g_U2T : (g_M2T + 2048);
            pld(nx, tid, pr);
            gemmS<32, 64, 2, 8>(h2s + 32 * p * P, cur, i0, joL2, aM2);
            pst(oth, tid, pr); __syncthreads();
            float* t = cur; cur = oth; oth = t;
        }
        // slots 8-9: U2
        ull aU2[4][2] = {};
#pragma unroll
        for (int p = 0; p < 2; p++) {
            const float* nx = p ? g_L1P : (g_U2T + 2048);
            pld(nx, tid, pr);
            gemmS<32, 64, 2, 8>(h2s + 32 * p * P, cur, i0, joL2, aU2);
            pst(oth, tid, pr); __syncthreads();
            float* t = cur; cur = oth; oth = t;
        }

        // ---- update h3, h2 (all reads of h2s/h3s done; next read after >=2 barriers) ----
        {
            int col = 2 * cg;
            float cc0 = sB[col], cc1 = sB[col + 1];
            float ub0 = sB[32 + col], ub1 = sB[32 + col + 1];
            float4 h0 = *reinterpret_cast<float4*>(h3s + col * P + i0);
            float4 h1v = *reinterpret_cast<float4*>(h3s + (col + 1) * P + i0);
#pragma unroll
            for (int r = 0; r < 4; r++) {
                float w0, w1, m0, m1, u0, u1;
                up2(aW3[r][0], w0, w1); up2(aM3[r][0], m0, m1); up2(aU3[r][0], u0, u1);
                addf4(h0, r, ftanh(w0 + m0 + cc0) + ftanh(u0 + ub0));
                addf4(h1v, r, ftanh(w1 + m1 + cc1) + ftanh(u1 + ub1));
            }
            *reinterpret_cast<float4*>(h3s + col * P + i0) = h0;
            *reinterpret_cast<float4*>(h3s + (col + 1) * P + i0) = h1v;
        }
#pragma unroll
        for (int p = 0; p < 2; p++) {
            int col = joL2[p];
            float cc0 = sB[64 + col], cc1 = sB[64 + col + 1];
            float ub0 = sB[128 + col], ub1 = sB[128 + col + 1];
            float4 h0 = *reinterpret_cast<float4*>(h2s + col * P + i0);
            float4 h1v = *reinterpret_cast<float4*>(h2s + (col + 1) * P + i0);
#pragma unroll
            for (int r = 0; r < 4; r++) {
                float w0, w1, m0, m1, u0, u1;
                up2(aW2[r][p], w0, w1); up2(aM2[r][p], m0, m1); up2(aU2[r][p], u0, u1);
                addf4(h0, r, ftanh(w0 + m0 + cc0) + ftanh(u0 + ub0));
                addf4(h1v, r, ftanh(w1 + m1 + cc1) + ftanh(u1 + ub1));
            }
            *reinterpret_cast<float4*>(h2s + col * P + i0) = h0;
            *reinterpret_cast<float4*>(h2s + (col + 1) * P + i0) = h1v;
        }

        // slots 10-25: L1 paired panels (-M1T | U1T), K=8 each
        ull aM1[4][4] = {}, aU1[4][4] = {};
#pragma unroll 1
        for (int p = 0; p < 16; p++) {
            const float* nx = (p < 15) ? (g_L1P + (p + 1) * 2048) : g_L3P;
            pld(nx, tid, pr);
            gemmP(h1s + 8 * p * P, cur, cur + 1024, i0, j4, aM1, aU1);
            pst(oth, tid, pr); __syncthreads();
            float* t = cur; cur = oth; oth = t;
        }

        // ---- update h1 ----
#pragma unroll
        for (int c = 0; c < 4; c++) {
            int col = (c < 2) ? (j4 + 2 * c) : (60 + j4 + 2 * c);
            float ub0 = sB[192 + col], ub1 = sB[192 + col + 1];
            float4 h0 = *reinterpret_cast<float4*>(h1s + col * P + i0);
            float4 h1v = *reinterpret_cast<float4*>(h1s + (col + 1) * P + i0);
#pragma unroll
            for (int r = 0; r < 4; r++) {
                float m0, m1, u0, u1;
                up2(aM1[r][c], m0, m1); up2(aU1[r][c], u0, u1);
                float xw0 = xws[(i0 + r) * 128 + col];
                float xw1 = xws[(i0 + r) * 128 + col + 1];
                addf4(h0, r, ftanh(xw0 + m0) + ftanh(u0 + ub0));
                addf4(h1v, r, ftanh(xw1 + m1) + ftanh(u1 + ub1));
            }
            *reinterpret_cast<float4*>(h1s + col * P + i0) = h0;
            *reinterpret_cast<float4*>(h1s + (col + 1) * P + i0) = h1v;
        }
        // no extra barrier: h1 writes are ordered before next step's first h1s read
        // (slot 2) by the slot-0 and slot-1 barriers.
    }
    __syncthreads();

    // ---- classifier: out = h3 @ clf^T + clf_b ----
    for (int idx = tid; idx < BT * 10; idx += NTHR) {
        int r = idx / 10, cc = idx - r * 10;
        float sacc = clfb[cc];
#pragma unroll
        for (int k = 0; k < 32; k++) sacc += h3s[k * P + r] * clfw[cc * 32 + k];
        out[(size_t)(row0 + r) * 10 + cc] = sacc;
    }
}

// ---------------- launch ----------------
extern "C" void kernel_launch(void* const* d_in, const int* in_sizes, int n_in,
                              void* d_out, int out_size) {
    const float* x    = (const float*)d_in[0];
    const float* W1w  = (const float*)d_in[1];
    const float* W1b  = (const float*)d_in[2];
    const float* U1w  = (const float*)d_in[3];
    const float* U1b  = (const float*)d_in[4];
    const float* W2w  = (const float*)d_in[5];
    const float* W2b  = (const float*)d_in[6];
    const float* U2w  = (const float*)d_in[7];
    const float* U2b  = (const float*)d_in[8];
    const float* W3w  = (const float*)d_in[9];
    const float* W3b  = (const float*)d_in[10];
    const float* U3w  = (const float*)d_in[11];
    const float* U3b  = (const float*)d_in[12];
    const float* fb3w = (const float*)d_in[13];
    const float* fb3b = (const float*)d_in[14];
    const float* fb2w = (const float*)d_in[15];
    const float* fb2b = (const float*)d_in[16];
    const float* fb1w = (const float*)d_in[17];
    const float* fb1b = (const float*)d_in[18];
    const float* clfw = (const float*)d_in[19];
    const float* clfb = (const float*)d_in[20];
    const int*   stp  = (const int*)d_in[21];

    int B = in_sizes[0] / 784;

    prep_all<<<256, 128>>>(W1w, W1b, U1w, W2w, W2b, U2w, W3w, W3b, U3w,
                           fb3w, fb3b, fb2w, fb2b, fb1w, fb1b);

    const int smem_bytes = 27840 * 4;   // 111360 -> 2 CTAs/SM
    cudaFuncSetAttribute(pcnet_main, cudaFuncAttributeMaxDynamicSharedMemorySize, smem_bytes);
    pcnet_main<<<B / BT, NTHR, smem_bytes>>>(x, U1b, U2b, U3b, clfw, clfb, stp, (float*)d_out);
}

// round 7
// speedup vs baseline: 2.3839x; 1.0145x over previous
#include <cuda_runtime.h>
#include <cstdint>

#define BT   64
#define P    68
#define NTHR 256
typedef unsigned long long ull;

// ---------------- persistent device scratch ----------------
__device__ __align__(16) float g_W1T[784*128];   // [k][j]
__device__ __align__(16) float g_L1P[32768];     // 16 pairs: [8][128] -M1T | [8][128] U1T
__device__ __align__(16) float g_W2T[128*64];
__device__ __align__(16) float g_M2T[64*64];     // negated
__device__ __align__(16) float g_U2T[64*64];
__device__ __align__(16) float g_L3P[4096];      // W3T[64*32] | -M3T[32*32] | U3T[32*32]
__device__ __align__(16) float g_c1[128];
__device__ __align__(16) float g_c2[64];
__device__ __align__(16) float g_c3[32];

// ---------------- helpers ----------------
__device__ __forceinline__ ull dup2(float x) {
    ull r; asm("mov.b64 %0, {%1, %1};" : "=l"(r) : "f"(x)); return r;
}
__device__ __forceinline__ void up2(ull v, float &lo, float &hi) {
    asm("mov.b64 {%0, %1}, %2;" : "=f"(lo), "=f"(hi) : "l"(v));
}
__device__ __forceinline__ void fma2(ull &d, ull a, ull b) {
    asm("fma.rn.f32x2 %0, %1, %2, %0;" : "+l"(d) : "l"(a), "l"(b));
}
// tanh(x) = 1 - 2/(1+e^{2x})  via MUFU.EX2 + MUFU.RCP (~1e-6 abs err)
__device__ __forceinline__ float ftanh(float x) {
    float e, r;
    asm("ex2.approx.ftz.f32 %0, %1;" : "=f"(e) : "f"(x * 2.8853900817779268f));
    asm("rcp.approx.ftz.f32 %0, %1;" : "=f"(r) : "f"(e + 1.0f));
    return fmaf(-2.0f, r, 1.0f);
}
__device__ __forceinline__ void addf4(float4 &v, int r, float d) {
    if (r == 0) v.x += d; else if (r == 1) v.y += d;
    else if (r == 2) v.z += d; else v.w += d;
}

// L1 paired dual GEMM, K=8 chunk. Thread: 8 rows (i0..i0+7) x 4 cols (j4..j4+3).
// Warp = 4 row-groups x 8 col-quads -> B loads 1 wavefront per matrix per k.
__device__ __forceinline__ void gemmL1(const float* __restrict__ A,
                                       const float* __restrict__ Bm,
                                       const float* __restrict__ Bu,
                                       int i0, int j4, ull (&m)[8][2], ull (&u)[8][2]) {
#pragma unroll
    for (int k = 0; k < 8; k++) {
        float4 a0 = *reinterpret_cast<const float4*>(A + k * P + i0);
        float4 a1 = *reinterpret_cast<const float4*>(A + k * P + i0 + 4);
        ulonglong2 bm = *reinterpret_cast<const ulonglong2*>(Bm + k * 128 + j4);
        ulonglong2 bu = *reinterpret_cast<const ulonglong2*>(Bu + k * 128 + j4);
        ull Ar[8] = {dup2(a0.x), dup2(a0.y), dup2(a0.z), dup2(a0.w),
                     dup2(a1.x), dup2(a1.y), dup2(a1.z), dup2(a1.w)};
#pragma unroll
        for (int r = 0; r < 8; r++) {
            fma2(m[r][0], Ar[r], bm.x);
            fma2(m[r][1], Ar[r], bm.y);
            fma2(u[r][0], Ar[r], bu.x);
            fma2(u[r][1], Ar[r], bu.y);
        }
    }
}

// 8 rows x 2 cols (1 f32x2) single-B GEMM
template<int K, int LDB, int UNR>
__device__ __forceinline__ void gemmR8(const float* __restrict__ A,
                                       const float* __restrict__ B,
                                       int i0, int j, ull (&acc)[8]) {
#pragma unroll UNR
    for (int k = 0; k < K; k++) {
        float4 a0 = *reinterpret_cast<const float4*>(A + k * P + i0);
        float4 a1 = *reinterpret_cast<const float4*>(A + k * P + i0 + 4);
        ull b = *reinterpret_cast<const ull*>(B + k * LDB + j);
        ull Ar[8] = {dup2(a0.x), dup2(a0.y), dup2(a0.z), dup2(a0.w),
                     dup2(a1.x), dup2(a1.y), dup2(a1.z), dup2(a1.w)};
#pragma unroll
        for (int r = 0; r < 8; r++) fma2(acc[r], Ar[r], b);
    }
}

// 4 rows x 2 cols (1 f32x2) single-B GEMM
template<int K, int LDB, int UNR>
__device__ __forceinline__ void gemmR4(const float* __restrict__ A,
                                       const float* __restrict__ B,
                                       int i0, int j, ull (&acc)[4]) {
#pragma unroll UNR
    for (int k = 0; k < K; k++) {
        float4 a = *reinterpret_cast<const float4*>(A + k * P + i0);
        ull b = *reinterpret_cast<const ull*>(B + k * LDB + j);
        ull Ar[4] = {dup2(a.x), dup2(a.y), dup2(a.z), dup2(a.w)};
#pragma unroll
        for (int r = 0; r < 4; r++) fma2(acc[r], Ar[r], b);
    }
}

// 2048-float panel staging: 2 float4 per thread (halves at +0 and +1024 floats)
__device__ __forceinline__ void pld(const float* __restrict__ src, int tid, float4 (&r)[2]) {
    r[0] = *reinterpret_cast<const float4*>(src + tid * 4);
    r[1] = *reinterpret_cast<const float4*>(src + 1024 + tid * 4);
}
__device__ __forceinline__ void pst(float* dst, int tid, const float4 (&r)[2]) {
    *reinterpret_cast<float4*>(dst + tid * 4) = r[0];
    *reinterpret_cast<float4*>(dst + 1024 + tid * 4) = r[1];
}

// ---------------- prep kernel ----------------
__global__ void prep_all(const float* __restrict__ W1w, const float* __restrict__ W1b,
                         const float* __restrict__ U1w,
                         const float* __restrict__ W2w, const float* __restrict__ W2b,
                         const float* __restrict__ U2w,
                         const float* __restrict__ W3w, const float* __restrict__ W3b,
                         const float* __restrict__ U3w,
                         const float* __restrict__ fb3w, const float* __restrict__ fb3b,
                         const float* __restrict__ fb2w, const float* __restrict__ fb2b,
                         const float* __restrict__ fb1w, const float* __restrict__ fb1b) {
    __shared__ float row_s[784];
    __shared__ float red_s[128];
    const int bid = blockIdx.x;
    const int tid = threadIdx.x;   // 128

    if (bid < 128) {
        const int j = bid;
        for (int d = tid; d < 784; d += 128) row_s[d] = W1w[j * 784 + d];
        __syncthreads();
        {
            const int k = tid;
            float s = 0.f;
#pragma unroll 4
            for (int d = 0; d < 784; d++) s += row_s[d] * fb1w[d * 128 + k];
            g_L1P[(k >> 3) * 2048 + (k & 7) * 128 + j] = -s;   // -M1T pair layout
        }
        float ps = 0.f;
        for (int d = tid; d < 784; d += 128) ps += row_s[d] * fb1b[d];
        red_s[tid] = ps;
        __syncthreads();
        for (int off = 64; off > 0; off >>= 1) {
            if (tid < off) red_s[tid] += red_s[tid + off];
            __syncthreads();
        }
        if (tid == 0) g_c1[j] = W1b[j] - red_s[0];
    } else if (bid < 192) {
        const int j = bid - 128;
        for (int d = tid; d < 128; d += 128) row_s[d] = W2w[j * 128 + d];
        __syncthreads();
        if (tid < 64) {
            const int k = tid;
            float s = 0.f;
#pragma unroll 4
            for (int d = 0; d < 128; d++) s += row_s[d] * fb2w[d * 64 + k];
            g_M2T[k * 64 + j] = -s;
        }
        float ps = 0.f;
        for (int d = tid; d < 128; d += 128) ps += row_s[d] * fb2b[d];
        red_s[tid] = ps;
        __syncthreads();
        for (int off = 64; off > 0; off >>= 1) {
            if (tid < off) red_s[tid] += red_s[tid + off];
            __syncthreads();
        }
        if (tid == 0) g_c2[j] = W2b[j] - red_s[0];
    } else if (bid < 224) {
        const int j = bid - 192;
        for (int d = tid; d < 64; d += 128) row_s[d] = W3w[j * 64 + d];
        __syncthreads();
        if (tid < 32) {
            const int k = tid;
            float s = 0.f;
#pragma unroll 4
            for (int d = 0; d < 64; d++) s += row_s[d] * fb3w[d * 32 + k];
            g_L3P[2048 + k * 32 + j] = -s;    // -M3T
        }
        float ps = 0.f;
        for (int d = tid; d < 64; d += 128) ps += row_s[d] * fb3b[d];
        red_s[tid] = ps;
        __syncthreads();
        for (int off = 64; off > 0; off >>= 1) {
            if (tid < off) red_s[tid] += red_s[tid + off];
            __syncthreads();
        }
        if (tid == 0) g_c3[j] = W3b[j] - red_s[0];
    } else {
        const int idx0 = (bid - 224) * 128 + tid;
        const int stride = 32 * 128;
        for (int t = idx0; t < 784 * 128; t += stride) {
            int k = t >> 7, j = t & 127;
            g_W1T[t] = W1w[j * 784 + k];
        }
        for (int t = idx0; t < 128 * 128; t += stride) {          // U1T pair layout
            int k = t >> 7, j = t & 127;
            g_L1P[(k >> 3) * 2048 + 1024 + (k & 7) * 128 + j] = U1w[j * 128 + k];
        }
        for (int t = idx0; t < 128 * 64; t += stride) {
            int k = t >> 6, j = t & 63;
            g_W2T[t] = W2w[j * 128 + k];
        }
        for (int t = idx0; t < 64 * 64; t += stride) {
            int k = t >> 6, j = t & 63;
            g_U2T[t] = U2w[j * 64 + k];
        }
        for (int t = idx0; t < 64 * 32; t += stride) {            // W3T
            int k = t >> 5, j = t & 31;
            g_L3P[t] = W3w[j * 64 + k];
        }
        for (int t = idx0; t < 32 * 32; t += stride) {            // U3T
            int k = t >> 5, j = t & 31;
            g_L3P[3072 + t] = U3w[j * 32 + k];
        }
    }
}

// ---------------- main kernel ----------------
// smem floats (27840 total = 111360 B, 2 CTAs/SM):
//   h1s[128*68]@0  h2s[64*68]@8704  h3s[32*68]@13056
//   xws[64][128]@15232 (8192)  buf0@23424(2048)  buf1@25472(2048)  sB@27520(320)
// phase-1 overlay: xck@0 [64][116]=7424, wck@7424 [112][128]=14336 (ends 21760 < buf0)
__global__ void __launch_bounds__(NTHR, 2)
pcnet_main(const float* __restrict__ x,
           const float* __restrict__ U1b, const float* __restrict__ U2b,
           const float* __restrict__ U3b,
           const float* __restrict__ clfw, const float* __restrict__ clfb,
           const int* __restrict__ steps_p,
           float* __restrict__ out) {
    extern __shared__ float sm[];
    float* h1s  = sm;
    float* h2s  = sm + 8704;
    float* h3s  = sm + 13056;
    float* xws  = sm + 15232;
    float* buf0 = sm + 23424;
    float* buf1 = sm + 25472;
    float* sB   = sm + 27520;
    float* xck  = sm;           // overlay
    float* wck  = sm + 7424;    // overlay

    const int tid  = threadIdx.x;
    const int row0 = blockIdx.x * BT;

    // gemm tile mapping: warp spans 4 row-groups x 8 col-quads -> 1-wf B loads
    const int wid  = tid >> 5, lane = tid & 31;
    const int rg   = ((wid & 1) << 2) + (lane >> 3);   // 0..7
    const int cq   = ((wid >> 1) << 3) + (lane & 7);   // 0..31
    const int i0   = rg * 8;
    const int j4   = cq * 4;      // L1: cols j4..j4+3
    const int j2   = cq * 2;      // L2: cols j2, j2+1
    const int rg3  = ((wid & 3) << 2) + (lane >> 3);   // 0..15
    const int cq3  = ((wid >> 2) << 3) + (lane & 7);   // 0..15
    const int i03  = rg3 * 4;
    const int j3   = cq3 * 2;     // L3: cols j3, j3+1

    int steps = *steps_p;
    if (steps < 0 || steps > 64) steps = 5;

    // stage biases + first panel (regions disjoint from phase-1 overlay)
    for (int t = tid; t < 320; t += NTHR) {
        float v;
        if (t < 32) v = g_c3[t];
        else if (t < 64) v = U3b[t - 32];
        else if (t < 128) v = g_c2[t - 64];
        else if (t < 192) v = U2b[t - 128];
        else v = U1b[t - 192];
        sB[t] = v;
    }
    for (int idx = tid; idx < 512; idx += NTHR)
        *reinterpret_cast<float4*>(buf0 + idx * 4) = *reinterpret_cast<const float4*>(g_L3P + idx * 4);

    // ---- phase 1: xw = x @ W1^T + c1 -> xws (legacy 4rx8c mapping) ----
    {
        const int p_i0 = (tid >> 4) * 4;
        const int p_j4 = (tid & 15) * 4;
        ull axw[4][4] = {};
        for (int c = 0; c < 7; c++) {
            for (int idx = tid; idx < 64 * 28; idx += NTHR) {
                int r = idx / 28, k4 = idx - r * 28;
                *reinterpret_cast<float4*>(xck + r * 116 + k4 * 4) =
                    *reinterpret_cast<const float4*>(x + (size_t)(row0 + r) * 784 + c * 112 + k4 * 4);
            }
            for (int idx = tid; idx < 112 * 32; idx += NTHR) {
                int kk = idx >> 5, jj = idx & 31;
                *reinterpret_cast<float4*>(wck + kk * 128 + jj * 4) =
                    *reinterpret_cast<const float4*>(g_W1T + (size_t)(c * 112 + kk) * 128 + jj * 4);
            }
            __syncthreads();
#pragma unroll 2
            for (int kk = 0; kk < 112; kk++) {
                ulonglong2 b0 = *reinterpret_cast<const ulonglong2*>(wck + kk * 128 + p_j4);
                ulonglong2 b1 = *reinterpret_cast<const ulonglong2*>(wck + kk * 128 + 64 + p_j4);
                ull Ar[4] = {dup2(xck[(p_i0 + 0) * 116 + kk]), dup2(xck[(p_i0 + 1) * 116 + kk]),
                             dup2(xck[(p_i0 + 2) * 116 + kk]), dup2(xck[(p_i0 + 3) * 116 + kk])};
#pragma unroll
                for (int r = 0; r < 4; r++) {
                    fma2(axw[r][0], Ar[r], b0.x);
                    fma2(axw[r][1], Ar[r], b0.y);
                    fma2(axw[r][2], Ar[r], b1.x);
                    fma2(axw[r][3], Ar[r], b1.y);
                }
            }
            __syncthreads();
        }
        float c1v[8];
#pragma unroll
        for (int t = 0; t < 4; t++) { c1v[t] = g_c1[p_j4 + t]; c1v[4 + t] = g_c1[64 + p_j4 + t]; }
#pragma unroll
        for (int r = 0; r < 4; r++) {
#pragma unroll
            for (int c = 0; c < 4; c++) {
                int col = (c < 2) ? (p_j4 + 2 * c) : (60 + p_j4 + 2 * c);
                float lo, hi;
                up2(axw[r][c], lo, hi);
                xws[(p_i0 + r) * 128 + col]     = lo + c1v[2 * c];
                xws[(p_i0 + r) * 128 + col + 1] = hi + c1v[2 * c + 1];
            }
        }
    }
    // zero states (overlays xck region; xws/buf/sB untouched)
    for (int i = tid; i < 15232; i += NTHR) sm[i] = 0.f;
    __syncthreads();

    float* cur = buf0;
    float* oth = buf1;

    // ---- step loop: 26 panel slots/step ----
    for (int s = 0; s < steps; s++) {
        float4 pr[2];
        ull aW3[4] = {}, aM3[4] = {}, aU3[4] = {};

        // slot 0: W3 (panel = W3T [64][32])
        pld(g_L3P + 2048, tid, pr);
        gemmR4<64, 32, 8>(h2s, cur, i03, j3, aW3);
        pst(oth, tid, pr); __syncthreads();
        { float* t = cur; cur = oth; oth = t; }

        // slot 1: M3|U3 (panel = [-M3T | U3T], 1024 each)
        pld(g_W2T, tid, pr);
        gemmR4<32, 32, 8>(h3s, cur, i03, j3, aM3);
        gemmR4<32, 32, 8>(h3s, cur + 1024, i03, j3, aU3);
        pst(oth, tid, pr); __syncthreads();
        { float* t = cur; cur = oth; oth = t; }

        // ---- update h3 (all h3s reads done at slot-1 barrier) ----
        {
            float cc0 = sB[j3], cc1 = sB[j3 + 1];
            float ub0 = sB[32 + j3], ub1 = sB[32 + j3 + 1];
            float4 h0 = *reinterpret_cast<float4*>(h3s + j3 * P + i03);
            float4 h1v = *reinterpret_cast<float4*>(h3s + (j3 + 1) * P + i03);
#pragma unroll
            for (int r = 0; r < 4; r++) {
                float w0, w1, m0, m1, u0, u1;
                up2(aW3[r], w0, w1); up2(aM3[r], m0, m1); up2(aU3[r], u0, u1);
                addf4(h0, r, ftanh(w0 + m0 + cc0) + ftanh(u0 + ub0));
                addf4(h1v, r, ftanh(w1 + m1 + cc1) + ftanh(u1 + ub1));
            }
            *reinterpret_cast<float4*>(h3s + j3 * P + i03) = h0;
            *reinterpret_cast<float4*>(h3s + (j3 + 1) * P + i03) = h1v;
        }

        // slots 2-5: W2 (4 chunks of 32 k)
        ull aW2[8] = {};
#pragma unroll
        for (int p = 0; p < 4; p++) {
            const float* nx = (p < 3) ? (g_W2T + (p + 1) * 2048) : g_M2T;
            pld(nx, tid, pr);
            gemmR8<32, 64, 8>(h1s + 32 * p * P, cur, i0, j2, aW2);
            pst(oth, tid, pr); __syncthreads();
            float* t = cur; cur = oth; oth = t;
        }
        // slots 6-7: M2
        ull aM2[8] = {};
#pragma unroll
        for (int p = 0; p < 2; p++) {
            const float* nx = p ? g_U2T : (g_M2T + 2048);
            pld(nx, tid, pr);
            gemmR8<32, 64, 8>(h2s + 32 * p * P, cur, i0, j2, aM2);
            pst(oth, tid, pr); __syncthreads();
            float* t = cur; cur = oth; oth = t;
        }
        // slots 8-9: U2
        ull aU2[8] = {};
#pragma unroll
        for (int p = 0; p < 2; p++) {
            const float* nx = p ? g_L1P : (g_U2T + 2048);
            pld(nx, tid, pr);
            gemmR8<32, 64, 8>(h2s + 32 * p * P, cur, i0, j2, aU2);
            pst(oth, tid, pr); __syncthreads();
            float* t = cur; cur = oth; oth = t;
        }

        // ---- update h2 (all h2s reads of this step done at slot-9 barrier) ----
        {
            float cc0 = sB[64 + j2], cc1 = sB[64 + j2 + 1];
            float ub0 = sB[128 + j2], ub1 = sB[128 + j2 + 1];
            float4 ha0 = *reinterpret_cast<float4*>(h2s + j2 * P + i0);
            float4 ha1 = *reinterpret_cast<float4*>(h2s + j2 * P + i0 + 4);
            float4 hb0 = *reinterpret_cast<float4*>(h2s + (j2 + 1) * P + i0);
            float4 hb1 = *reinterpret_cast<float4*>(h2s + (j2 + 1) * P + i0 + 4);
#pragma unroll
            for (int r = 0; r < 8; r++) {
                float w0, w1, m0, m1, u0, u1;
                up2(aW2[r], w0, w1); up2(aM2[r], m0, m1); up2(aU2[r], u0, u1);
                float d0 = ftanh(w0 + m0 + cc0) + ftanh(u0 + ub0);
                float d1 = ftanh(w1 + m1 + cc1) + ftanh(u1 + ub1);
                if (r < 4) { addf4(ha0, r, d0); addf4(hb0, r, d1); }
                else       { addf4(ha1, r - 4, d0); addf4(hb1, r - 4, d1); }
            }
            *reinterpret_cast<float4*>(h2s + j2 * P + i0)           = ha0;
            *reinterpret_cast<float4*>(h2s + j2 * P + i0 + 4)       = ha1;
            *reinterpret_cast<float4*>(h2s + (j2 + 1) * P + i0)     = hb0;
            *reinterpret_cast<float4*>(h2s + (j2 + 1) * P + i0 + 4) = hb1;
        }

        // slots 10-25: L1 paired panels (-M1T | U1T), K=8 each
        ull aM1[8][2] = {}, aU1[8][2] = {};
#pragma unroll 1
        for (int p = 0; p < 16; p++) {
            const float* nx = (p < 15) ? (g_L1P + (p + 1) * 2048) : g_L3P;
            pld(nx, tid, pr);
            gemmL1(h1s + 8 * p * P, cur, cur + 1024, i0, j4, aM1, aU1);
            pst(oth, tid, pr); __syncthreads();
            float* t = cur; cur = oth; oth = t;
        }

        // ---- update h1 ----
#pragma unroll
        for (int cp = 0; cp < 2; cp++) {
            int col = j4 + 2 * cp;
            float ub0 = sB[192 + col], ub1 = sB[192 + col + 1];
            float4 ha0 = *reinterpret_cast<float4*>(h1s + col * P + i0);
            float4 ha1 = *reinterpret_cast<float4*>(h1s + col * P + i0 + 4);
            float4 hb0 = *reinterpret_cast<float4*>(h1s + (col + 1) * P + i0);
            float4 hb1 = *reinterpret_cast<float4*>(h1s + (col + 1) * P + i0 + 4);
#pragma unroll
            for (int r = 0; r < 8; r++) {
                float m0, m1, u0, u1, xw0, xw1;
                up2(aM1[r][cp], m0, m1); up2(aU1[r][cp], u0, u1);
                up2(*reinterpret_cast<const ull*>(xws + (i0 + r) * 128 + col), xw0, xw1);
                float d0 = ftanh(xw0 + m0) + ftanh(u0 + ub0);
                float d1 = ftanh(xw1 + m1) + ftanh(u1 + ub1);
                if (r < 4) { addf4(ha0, r, d0); addf4(hb0, r, d1); }
                else       { addf4(ha1, r - 4, d0); addf4(hb1, r - 4, d1); }
            }
            *reinterpret_cast<float4*>(h1s + col * P + i0)           = ha0;
            *reinterpret_cast<float4*>(h1s + col * P + i0 + 4)       = ha1;
            *reinterpret_cast<float4*>(h1s + (col + 1) * P + i0)     = hb0;
            *reinterpret_cast<float4*>(h1s + (col + 1) * P + i0 + 4) = hb1;
        }
        // h1 writes ordered before next step's first h1s read (slot 2) by the
        // slot-0 and slot-1 barriers of the next iteration.
    }
    __syncthreads();

    // ---- classifier: out = h3 @ clf^T + clf_b ----
    for (int idx = tid; idx < BT * 10; idx += NTHR) {
        int r = idx / 10, cc = idx - r * 10;
        float sacc = clfb[cc];
#pragma unroll
        for (int k = 0; k < 32; k++) sacc += h3s[k * P + r] * clfw[cc * 32 + k];
        out[(size_t)(row0 + r) * 10 + cc] = sacc;
    }
}

// ---------------- launch ----------------
extern "C" void kernel_launch(void* const* d_in, const int* in_sizes, int n_in,
                              void* d_out, int out_size) {
    const float* x    = (const float*)d_in[0];
    const float* W1w  = (const float*)d_in[1];
    const float* W1b  = (const float*)d_in[2];
    const float* U1w  = (const float*)d_in[3];
    const float* U1b  = (const float*)d_in[4];
    const float* W2w  = (const float*)d_in[5];
    const float* W2b  = (const float*)d_in[6];
    const float* U2w  = (const float*)d_in[7];
    const float* U2b  = (const float*)d_in[8];
    const float* W3w  = (const float*)d_in[9];
    const float* W3b  = (const float*)d_in[10];
    const float* U3w  = (const float*)d_in[11];
    const float* U3b  = (const float*)d_in[12];
    const float* fb3w = (const float*)d_in[13];
    const float* fb3b = (const float*)d_in[14];
    const float* fb2w = (const float*)d_in[15];
    const float* fb2b = (const float*)d_in[16];
    const float* fb1w = (const float*)d_in[17];
    const float* fb1b = (const float*)d_in[18];
    const float* clfw = (const float*)d_in[19];
    const float* clfb = (const float*)d_in[20];
    const int*   stp  = (const int*)d_in[21];

    int B = in_sizes[0] / 784;

    prep_all<<<256, 128>>>(W1w, W1b, U1w, W2w, W2b, U2w, W3w, W3b, U3w,
                           fb3w, fb3b, fb2w, fb2b, fb1w, fb1b);

    const int smem_bytes = 27840 * 4;   // 111360 -> 2 CTAs/SM
    cudaFuncSetAttribute(pcnet_main, cudaFuncAttributeMaxDynamicSharedMemorySize, smem_bytes);
    pcnet_main<<<B / BT, NTHR, smem_bytes>>>(x, U1b, U2b, U3b, clfw, clfb, stp, (float*)d_out);
}